// round 2
// baseline (speedup 1.0000x reference)
#include <cuda_runtime.h>
#include <cstdint>

#define B_SIZE 131072
#define NAG 8
#define HXS 64
#define ENC 128
#define ACTS 5

// scratch (device globals: no allocation allowed)
__device__ float g_h[NAG * HXS * B_SIZE];   // layout [n][o][b], 256 MiB
__device__ float g_comm[NAG * HXS];
__device__ float g_pre2[NAG * HXS];

__device__ __forceinline__ unsigned long long pack2(float x, float y) {
    unsigned long long r;
    asm("mov.b64 %0, {%1, %2};" : "=l"(r) : "f"(x), "f"(y));
    return r;
}
__device__ __forceinline__ void unpack2(unsigned long long v, float &x, float &y) {
    asm("mov.b64 {%0, %1}, %2;" : "=f"(x), "=f"(y) : "l"(v));
}
__device__ __forceinline__ void ffma2(unsigned long long &d, unsigned long long a,
                                      unsigned long long b) {
    asm("fma.rn.f32x2 %0, %1, %2, %0;" : "+l"(d) : "l"(a), "l"(b));
}
__device__ __forceinline__ float fast_tanh(float x) {
    float r;
    asm("tanh.approx.f32 %0, %1;" : "=f"(r) : "f"(x));
    return r;
}

__global__ void k_zero() {
    if (threadIdx.x < NAG * HXS) g_comm[threadIdx.x] = 0.f;
}

// Encoder: h = relu(relu(obs@W1+b1)@W2+b2), store h, and accumulate comm partials.
// grid (B/256, NAG), 256 threads, thread = one batch element for agent n = blockIdx.y
__global__ __launch_bounds__(256) void k_enc(
    const float* __restrict__ obs, const float* __restrict__ W1,
    const float* __restrict__ b1, const float* __restrict__ W2,
    const float* __restrict__ b2)
{
    extern __shared__ float sm[];
    float* sW1 = sm;                  // [2][128]
    float* sB1 = sW1 + 2 * ENC;       // [128]
    float* sW2 = sB1 + ENC;           // [128][64]  (16B-aligned offset: 384 floats)
    float* sB2 = sW2 + ENC * HXS;     // [64]
    float* sH  = sB2 + HXS;           // [64][257] transposed+padded h tile
    float* sC  = sH + HXS * 257;      // [8][257]  coef[i][bb] = mask[i][n]/J[i]

    const int n   = blockIdx.y;
    const int tid = threadIdx.x;
    const int b   = blockIdx.x * 256 + tid;

    for (int i = tid; i < 2 * ENC; i += 256)   sW1[i] = W1[n * 2 * ENC + i];
    for (int i = tid; i < ENC; i += 256)       sB1[i] = b1[n * ENC + i];
    for (int i = tid; i < ENC * HXS; i += 256) sW2[i] = W2[n * ENC * HXS + i];
    if (tid < HXS) sB2[tid] = b2[n * HXS + tid];
    __syncthreads();

    const float o0 = obs[(b * NAG + n) * 2 + 0];
    const float o1 = obs[(b * NAG + n) * 2 + 1];

    unsigned long long acc[HXS / 2];
#pragma unroll
    for (int p = 0; p < HXS / 2; p++) acc[p] = pack2(sB2[2 * p], sB2[2 * p + 1]);

#pragma unroll 4
    for (int e = 0; e < ENC; e++) {
        float h1 = fmaf(o0, sW1[e], fmaf(o1, sW1[ENC + e], sB1[e]));
        h1 = fmaxf(h1, 0.f);
        unsigned long long hh = pack2(h1, h1);
        const ulonglong2* wr = (const ulonglong2*)(sW2 + e * HXS);
#pragma unroll
        for (int p = 0; p < 16; p++) {
            ulonglong2 w = wr[p];
            ffma2(acc[2 * p], hh, w.x);
            ffma2(acc[2 * p + 1], hh, w.y);
        }
    }

    // relu, write h to global [n][o][b] (coalesced) and to smem tile
#pragma unroll
    for (int p = 0; p < HXS / 2; p++) {
        float x, y;
        unpack2(acc[p], x, y);
        x = fmaxf(x, 0.f);
        y = fmaxf(y, 0.f);
        const int o = 2 * p;
        g_h[(n * HXS + o) * B_SIZE + b]     = x;
        g_h[(n * HXS + o + 1) * B_SIZE + b] = y;
        sH[o * 257 + tid]       = x;
        sH[(o + 1) * 257 + tid] = y;
    }

    // communication coefficients: coef_i = mask[i][n] / J[i]
    float px[NAG], py[NAG];
#pragma unroll
    for (int j = 0; j < NAG; j++) {
        px[j] = obs[(b * NAG + j) * 2 + 0] * 2.0f;  // GRID[0]-1
        py[j] = obs[(b * NAG + j) * 2 + 1] * 6.0f;  // GRID[1]-1
    }
#pragma unroll
    for (int i = 0; i < NAG; i++) {
        float J = 0.f, mn = 0.f;
#pragma unroll
        for (int j = 0; j < NAG; j++) {
            float d = fabsf(px[i] - px[j]) + fabsf(py[i] - py[j]);
            bool msk = (d > 0.f) && (d < 2.0f);
            J += msk ? 1.f : 0.f;
            if (j == n) mn = msk ? 1.f : 0.f;
        }
        if (J <= 0.f) J = 1.f;
        sC[i * 257 + tid] = mn / J;
    }
    __syncthreads();

    // per-block 8x64 reduction GEMM: partial[i][o] = sum_bb coef[i][bb]*h[bb][o]
    const int o  = tid & 63;
    const int i0 = tid >> 6;  // 0..3, second pair at i0+4
    float s0 = 0.f, s1 = 0.f;
#pragma unroll 8
    for (int bb = 0; bb < 256; bb++) {
        float hv = sH[o * 257 + bb];
        s0 = fmaf(sC[i0 * 257 + bb], hv, s0);
        s1 = fmaf(sC[(i0 + 4) * 257 + bb], hv, s1);
    }
    atomicAdd(&g_comm[i0 * HXS + o], s0);
    atomicAdd(&g_comm[(i0 + 4) * HXS + o], s1);
}

// pre2[n][o] = bc[n][o] + sum_h comm[n][h] * Wc[n][HX+h][o]
__global__ void k_pre(const float* __restrict__ Wc, const float* __restrict__ bc) {
    const int n = blockIdx.x, o = threadIdx.x;
    float s = bc[n * HXS + o];
#pragma unroll 8
    for (int h = 0; h < HXS; h++)
        s = fmaf(g_comm[n * HXS + h], Wc[n * 2 * HXS * HXS + (HXS + h) * HXS + o], s);
    g_pre2[n * HXS + o] = s;
}

// Decoder: h2 = tanh(h @ Wc_low + pre2); q = h2 @ Wd + bd
__global__ __launch_bounds__(256) void k_dec(
    const float* __restrict__ Wc, const float* __restrict__ Wd,
    const float* __restrict__ bd, float* __restrict__ out)
{
    __shared__ __align__(16) float sWc[HXS * HXS];
    __shared__ float sWd[HXS * ACTS];
    __shared__ float sP[HXS];
    __shared__ float sBd[ACTS];

    const int n   = blockIdx.y;
    const int tid = threadIdx.x;
    const int b   = blockIdx.x * 256 + tid;

    for (int i = tid; i < HXS * HXS; i += 256)  sWc[i] = Wc[n * 2 * HXS * HXS + i];
    for (int i = tid; i < HXS * ACTS; i += 256) sWd[i] = Wd[n * HXS * ACTS + i];
    if (tid < HXS)  sP[tid]  = g_pre2[n * HXS + tid];
    if (tid < ACTS) sBd[tid] = bd[n * ACTS + tid];
    __syncthreads();

    unsigned long long acc[HXS / 2];
#pragma unroll
    for (int p = 0; p < HXS / 2; p++) acc[p] = pack2(sP[2 * p], sP[2 * p + 1]);

#pragma unroll 8
    for (int i = 0; i < HXS; i++) {
        float hv = g_h[(n * HXS + i) * B_SIZE + b];
        unsigned long long hh = pack2(hv, hv);
        const ulonglong2* wr = (const ulonglong2*)(sWc + i * HXS);
#pragma unroll
        for (int p = 0; p < 16; p++) {
            ulonglong2 w = wr[p];
            ffma2(acc[2 * p], hh, w.x);
            ffma2(acc[2 * p + 1], hh, w.y);
        }
    }

    float q[ACTS];
#pragma unroll
    for (int a = 0; a < ACTS; a++) q[a] = sBd[a];
#pragma unroll
    for (int p = 0; p < HXS / 2; p++) {
        float x, y;
        unpack2(acc[p], x, y);
        x = fast_tanh(x);
        y = fast_tanh(y);
        const int o = 2 * p;
#pragma unroll
        for (int a = 0; a < ACTS; a++) {
            q[a] = fmaf(x, sWd[o * ACTS + a], q[a]);
            q[a] = fmaf(y, sWd[(o + 1) * ACTS + a], q[a]);
        }
    }
#pragma unroll
    for (int a = 0; a < ACTS; a++) out[(b * NAG + n) * ACTS + a] = q[a];
}

extern "C" void kernel_launch(void* const* d_in, const int* in_sizes, int n_in,
                              void* d_out, int out_size)
{
    const float* obs = (const float*)d_in[0];
    const float* W1  = (const float*)d_in[1];
    const float* b1  = (const float*)d_in[2];
    const float* W2  = (const float*)d_in[3];
    const float* b2  = (const float*)d_in[4];
    const float* Wc  = (const float*)d_in[5];
    const float* bc  = (const float*)d_in[6];
    const float* Wd  = (const float*)d_in[7];
    const float* bd  = (const float*)d_in[8];
    float* out = (float*)d_out;

    const int SMEM1 = (2 * ENC + ENC + ENC * HXS + HXS + HXS * 257 + 8 * 257) * sizeof(float);
    cudaFuncSetAttribute(k_enc, cudaFuncAttributeMaxDynamicSharedMemorySize, SMEM1);

    k_zero<<<1, 512>>>();
    k_enc<<<dim3(B_SIZE / 256, NAG), 256, SMEM1>>>(obs, W1, b1, W2, b2);
    k_pre<<<NAG, HXS>>>(Wc, bc);
    k_dec<<<dim3(B_SIZE / 256, NAG), 256>>>(Wc, Wd, bd, out);
}

// round 3
// speedup vs baseline: 1.0104x; 1.0104x over previous
#include <cuda_runtime.h>
#include <cstdint>

#define B_SIZE 131072
#define NAG 8
#define HXS 64
#define ENC 128
#define ACTS 5

// scratch (device globals: no allocation allowed)
__device__ float g_h[NAG * HXS * B_SIZE];   // layout [n][o][b], 256 MiB
__device__ float g_comm[NAG * HXS];
__device__ float g_pre2[NAG * HXS];

__device__ __forceinline__ unsigned long long pack2(float x, float y) {
    unsigned long long r;
    asm("mov.b64 %0, {%1, %2};" : "=l"(r) : "f"(x), "f"(y));
    return r;
}
__device__ __forceinline__ void unpack2(unsigned long long v, float &x, float &y) {
    asm("mov.b64 {%0, %1}, %2;" : "=f"(x), "=f"(y) : "l"(v));
}
__device__ __forceinline__ void ffma2(unsigned long long &d, unsigned long long a,
                                      unsigned long long b) {
    asm("fma.rn.f32x2 %0, %1, %2, %0;" : "+l"(d) : "l"(a), "l"(b));
}
__device__ __forceinline__ float fast_tanh(float x) {
    float r;
    asm("tanh.approx.f32 %0, %1;" : "=f"(r) : "f"(x));
    return r;
}

__global__ void k_zero() {
    if (threadIdx.x < NAG * HXS) g_comm[threadIdx.x] = 0.f;
}

// Encoder: h = relu(relu(obs@W1+b1)@W2+b2), store h, and accumulate comm partials.
// grid (B/256, NAG), 256 threads, thread = one batch element for agent n = blockIdx.y
__global__ __launch_bounds__(256) void k_enc(
    const float* __restrict__ obs, const float* __restrict__ W1,
    const float* __restrict__ b1, const float* __restrict__ W2,
    const float* __restrict__ b2)
{
    extern __shared__ float sm[];
    float* sW1 = sm;                  // [2][128]
    float* sB1 = sW1 + 2 * ENC;       // [128]
    float* sW2 = sB1 + ENC;           // [128][64]  (16B-aligned offset: 384 floats)
    float* sB2 = sW2 + ENC * HXS;     // [64]
    float* sH  = sB2 + HXS;           // [64][257] transposed+padded h tile
    float* sC  = sH + HXS * 257;      // [8][257]  coef[i][bb] = mask[i][n]/J[i]

    const int n   = blockIdx.y;
    const int tid = threadIdx.x;
    const int b   = blockIdx.x * 256 + tid;

    for (int i = tid; i < 2 * ENC; i += 256)   sW1[i] = W1[n * 2 * ENC + i];
    for (int i = tid; i < ENC; i += 256)       sB1[i] = b1[n * ENC + i];
    for (int i = tid; i < ENC * HXS; i += 256) sW2[i] = W2[n * ENC * HXS + i];
    if (tid < HXS) sB2[tid] = b2[n * HXS + tid];
    __syncthreads();

    const float o0 = obs[(b * NAG + n) * 2 + 0];
    const float o1 = obs[(b * NAG + n) * 2 + 1];

    unsigned long long acc[HXS / 2];
#pragma unroll
    for (int p = 0; p < HXS / 2; p++) acc[p] = pack2(sB2[2 * p], sB2[2 * p + 1]);

#pragma unroll 4
    for (int e = 0; e < ENC; e++) {
        float h1 = fmaf(o0, sW1[e], fmaf(o1, sW1[ENC + e], sB1[e]));
        h1 = fmaxf(h1, 0.f);
        unsigned long long hh = pack2(h1, h1);
        const ulonglong2* wr = (const ulonglong2*)(sW2 + e * HXS);
#pragma unroll
        for (int p = 0; p < 16; p++) {
            ulonglong2 w = wr[p];
            ffma2(acc[2 * p], hh, w.x);
            ffma2(acc[2 * p + 1], hh, w.y);
        }
    }

    // relu, write h to global [n][o][b] (coalesced) and to smem tile
#pragma unroll
    for (int p = 0; p < HXS / 2; p++) {
        float x, y;
        unpack2(acc[p], x, y);
        x = fmaxf(x, 0.f);
        y = fmaxf(y, 0.f);
        const int o = 2 * p;
        g_h[(n * HXS + o) * B_SIZE + b]     = x;
        g_h[(n * HXS + o + 1) * B_SIZE + b] = y;
        sH[o * 257 + tid]       = x;
        sH[(o + 1) * 257 + tid] = y;
    }

    // communication coefficients: coef_i = mask[i][n] / J[i]
    float px[NAG], py[NAG];
#pragma unroll
    for (int j = 0; j < NAG; j++) {
        px[j] = obs[(b * NAG + j) * 2 + 0] * 2.0f;  // GRID[0]-1
        py[j] = obs[(b * NAG + j) * 2 + 1] * 6.0f;  // GRID[1]-1
    }
#pragma unroll
    for (int i = 0; i < NAG; i++) {
        float J = 0.f, mn = 0.f;
#pragma unroll
        for (int j = 0; j < NAG; j++) {
            float d = fabsf(px[i] - px[j]) + fabsf(py[i] - py[j]);
            bool msk = (d > 0.f) && (d < 2.0f);
            J += msk ? 1.f : 0.f;
            if (j == n) mn = msk ? 1.f : 0.f;
        }
        if (J <= 0.f) J = 1.f;
        sC[i * 257 + tid] = mn / J;
    }
    __syncthreads();

    // per-block 8x64 reduction GEMM: partial[i][o] = sum_bb coef[i][bb]*h[bb][o]
    const int o  = tid & 63;
    const int i0 = tid >> 6;  // 0..3, second pair at i0+4
    float s0 = 0.f, s1 = 0.f;
#pragma unroll 8
    for (int bb = 0; bb < 256; bb++) {
        float hv = sH[o * 257 + bb];
        s0 = fmaf(sC[i0 * 257 + bb], hv, s0);
        s1 = fmaf(sC[(i0 + 4) * 257 + bb], hv, s1);
    }
    atomicAdd(&g_comm[i0 * HXS + o], s0);
    atomicAdd(&g_comm[(i0 + 4) * HXS + o], s1);
}

// pre2[n][o] = bc[n][o] + sum_h comm[n][h] * Wc[n][HX+h][o]
__global__ void k_pre(const float* __restrict__ Wc, const float* __restrict__ bc) {
    const int n = blockIdx.x, o = threadIdx.x;
    float s = bc[n * HXS + o];
#pragma unroll 8
    for (int h = 0; h < HXS; h++)
        s = fmaf(g_comm[n * HXS + h], Wc[n * 2 * HXS * HXS + (HXS + h) * HXS + o], s);
    g_pre2[n * HXS + o] = s;
}

// Decoder: h2 = tanh(h @ Wc_low + pre2); q = h2 @ Wd + bd
__global__ __launch_bounds__(256) void k_dec(
    const float* __restrict__ Wc, const float* __restrict__ Wd,
    const float* __restrict__ bd, float* __restrict__ out)
{
    __shared__ __align__(16) float sWc[HXS * HXS];
    __shared__ float sWd[HXS * ACTS];
    __shared__ float sP[HXS];
    __shared__ float sBd[ACTS];

    const int n   = blockIdx.y;
    const int tid = threadIdx.x;
    const int b   = blockIdx.x * 256 + tid;

    for (int i = tid; i < HXS * HXS; i += 256)  sWc[i] = Wc[n * 2 * HXS * HXS + i];
    for (int i = tid; i < HXS * ACTS; i += 256) sWd[i] = Wd[n * HXS * ACTS + i];
    if (tid < HXS)  sP[tid]  = g_pre2[n * HXS + tid];
    if (tid < ACTS) sBd[tid] = bd[n * ACTS + tid];
    __syncthreads();

    unsigned long long acc[HXS / 2];
#pragma unroll
    for (int p = 0; p < HXS / 2; p++) acc[p] = pack2(sP[2 * p], sP[2 * p + 1]);

#pragma unroll 8
    for (int i = 0; i < HXS; i++) {
        float hv = g_h[(n * HXS + i) * B_SIZE + b];
        unsigned long long hh = pack2(hv, hv);
        const ulonglong2* wr = (const ulonglong2*)(sWc + i * HXS);
#pragma unroll
        for (int p = 0; p < 16; p++) {
            ulonglong2 w = wr[p];
            ffma2(acc[2 * p], hh, w.x);
            ffma2(acc[2 * p + 1], hh, w.y);
        }
    }

    float q[ACTS];
#pragma unroll
    for (int a = 0; a < ACTS; a++) q[a] = sBd[a];
#pragma unroll
    for (int p = 0; p < HXS / 2; p++) {
        float x, y;
        unpack2(acc[p], x, y);
        x = fast_tanh(x);
        y = fast_tanh(y);
        const int o = 2 * p;
#pragma unroll
        for (int a = 0; a < ACTS; a++) {
            q[a] = fmaf(x, sWd[o * ACTS + a], q[a]);
            q[a] = fmaf(y, sWd[(o + 1) * ACTS + a], q[a]);
        }
    }
#pragma unroll
    for (int a = 0; a < ACTS; a++) out[(b * NAG + n) * ACTS + a] = q[a];
}

extern "C" void kernel_launch(void* const* d_in, const int* in_sizes, int n_in,
                              void* d_out, int out_size)
{
    const float* obs = (const float*)d_in[0];
    const float* W1  = (const float*)d_in[1];
    const float* b1  = (const float*)d_in[2];
    const float* W2  = (const float*)d_in[3];
    const float* b2  = (const float*)d_in[4];
    const float* Wc  = (const float*)d_in[5];
    const float* bc  = (const float*)d_in[6];
    const float* Wd  = (const float*)d_in[7];
    const float* bd  = (const float*)d_in[8];
    float* out = (float*)d_out;

    const int SMEM1 = (2 * ENC + ENC + ENC * HXS + HXS + HXS * 257 + 8 * 257) * sizeof(float);
    cudaFuncSetAttribute(k_enc, cudaFuncAttributeMaxDynamicSharedMemorySize, SMEM1);

    k_zero<<<1, 512>>>();
    k_enc<<<dim3(B_SIZE / 256, NAG), 256, SMEM1>>>(obs, W1, b1, W2, b2);
    k_pre<<<NAG, HXS>>>(Wc, bc);
    k_dec<<<dim3(B_SIZE / 256, NAG), 256>>>(Wc, Wd, bd, out);
}